// round 1
// baseline (speedup 1.0000x reference)
#include <cuda_runtime.h>
#include <math.h>

#define NBATCH 4
#define NC     256
#define HW     65536
#define WIMG   256
#define NSP    1024
#define HID    128
#define ODIM   64
#define INV_T  10.0f

#define NT_TILES 8          // pixel tiles for scatter
#define CG       32         // channels per scatter block
#define NCG      (NC/CG)    // 8

// ---------------- scratch (device globals; no allocation allowed) ----------------
__device__ float g_spcl_cnt[NBATCH * NSP];
__device__ float g_spcl_adj[(size_t)NBATCH * NSP * NSP];              // 16 MB
__device__ float g_spcl_invdeg[NBATCH * NSP];
__device__ float g_spcl_part[(size_t)NT_TILES * NBATCH * NC * NSP];   // 32 MB
__device__ float g_spcl_spf[(size_t)NBATCH * NC * NSP];               // [b][c][s] 4 MB
__device__ float g_spcl_pT[(size_t)NBATCH * HID * NSP];               // [b][j][s]
__device__ float g_spcl_h1[(size_t)NBATCH * NSP * HID];
__device__ float g_spcl_h2[(size_t)NBATCH * NSP * HID];
__device__ float g_spcl_z1[(size_t)NBATCH * NSP * ODIM];
__device__ float g_spcl_z2[(size_t)NBATCH * NSP * ODIM];
__device__ float g_spcl_sim[(size_t)NBATCH * NSP * NSP];              // 16 MB

// ---------------- zero: adj + cnt + out --------------------------------------
__global__ __launch_bounds__(256) void zero_kernel(float* d_out) {
    size_t gid = (size_t)blockIdx.x * 256 + threadIdx.x;   // 4096*256 = 1,048,576
    float4 z = make_float4(0.f, 0.f, 0.f, 0.f);
    *(float4*)(g_spcl_adj + gid * 4) = z;
    if (gid < (NBATCH * NSP) / 4) *(float4*)(g_spcl_cnt + gid * 4) = z;
    if (gid == 0) d_out[0] = 0.f;
}

// ---------------- counts + binary adjacency ----------------------------------
__global__ __launch_bounds__(256) void count_adj_kernel(const int* __restrict__ idx) {
    int b = blockIdx.y;
    int p = blockIdx.x * 256 + threadIdx.x;
    const int* ib = idx + (size_t)b * HW;
    int s = ib[p];
    atomicAdd(&g_spcl_cnt[b * NSP + s], 1.0f);
    float* adjb = g_spcl_adj + (size_t)b * NSP * NSP;
    if ((p & (WIMG - 1)) < WIMG - 1) {          // right neighbor
        int s2 = ib[p + 1];
        if (s2 != s) { adjb[(size_t)s * NSP + s2] = 1.f; adjb[(size_t)s2 * NSP + s] = 1.f; }
    }
    if (p < HW - WIMG) {                        // down neighbor
        int s2 = ib[p + WIMG];
        if (s2 != s) { adjb[(size_t)s * NSP + s2] = 1.f; adjb[(size_t)s2 * NSP + s] = 1.f; }
    }
    if (p < NSP) adjb[(size_t)p * NSP + p] = 1.f;   // eye
}

// ---------------- scatter-aggregate features ---------------------------------
// grid: (NT_TILES, NCG, NBATCH), 256 threads, dyn smem = 32*1024*4 + 2048*2
__global__ __launch_bounds__(256) void scatter_kernel(const float* __restrict__ feat,
                                                      const int* __restrict__ idx) {
    extern __shared__ float smem[];
    float* acc = smem;                                        // [CG][NSP]
    unsigned short* sidx = (unsigned short*)(smem + CG * NSP);// [2048]
    int tid  = threadIdx.x;
    int tile = blockIdx.x, cg = blockIdx.y, b = blockIdx.z;

    for (int i = tid; i < CG * NSP; i += 256) acc[i] = 0.f;

    const int TILE_PIX = HW / NT_TILES;   // 8192
    int p0 = tile * TILE_PIX;
    const float* fb = feat + ((size_t)b * NC + cg * CG) * HW;
    const int*   ib = idx + (size_t)b * HW;

    for (int ch0 = 0; ch0 < TILE_PIX; ch0 += 2048) {
        __syncthreads();
        #pragma unroll
        for (int t = 0; t < 2; t++) {
            int4 iv = ((const int4*)(ib + p0 + ch0))[tid + t * 256];
            int base = (tid + t * 256) * 4;
            sidx[base + 0] = (unsigned short)iv.x;
            sidx[base + 1] = (unsigned short)iv.y;
            sidx[base + 2] = (unsigned short)iv.z;
            sidx[base + 3] = (unsigned short)iv.w;
        }
        __syncthreads();
        for (int cc = 0; cc < CG; cc++) {
            const float* fc = fb + (size_t)cc * HW + p0 + ch0;
            float* accc = acc + cc * NSP;
            #pragma unroll
            for (int t = 0; t < 2; t++) {
                float4  fv = ((const float4*)fc)[tid + t * 256];
                ushort4 sv = ((const ushort4*)sidx)[tid + t * 256];
                atomicAdd(&accc[sv.x], fv.x);
                atomicAdd(&accc[sv.y], fv.y);
                atomicAdd(&accc[sv.z], fv.z);
                atomicAdd(&accc[sv.w], fv.w);
            }
        }
    }
    __syncthreads();
    float* dst = g_spcl_part + (((size_t)tile * NBATCH + b) * NC + cg * CG) * NSP;
    for (int i = tid; i < CG * NSP; i += 256) dst[i] = acc[i];
}

// ---------------- reduce partials -> mean features [b][c][s] ------------------
__global__ __launch_bounds__(256) void reduce_kernel() {
    size_t i = (size_t)blockIdx.x * 256 + threadIdx.x;   // 4096*256 = 1M
    int s = (int)(i & (NSP - 1));
    int b = (int)(i >> 18);                              // 256*1024 = 2^18
    float sum = 0.f;
    #pragma unroll
    for (int t = 0; t < NT_TILES; t++)
        sum += g_spcl_part[(size_t)t * (NBATCH * NC * NSP) + i];
    float c = g_spcl_cnt[b * NSP + s];
    g_spcl_spf[i] = (c > 0.f) ? (sum / c) : 0.f;
}

// ---------------- invdeg = rsqrt(rowsum(adj)) ---------------------------------
__global__ __launch_bounds__(256) void invdeg_kernel() {
    int b = blockIdx.y;
    int row = blockIdx.x * 8 + (threadIdx.x >> 5);
    int lane = threadIdx.x & 31;
    const float* r = g_spcl_adj + ((size_t)b * NSP + row) * NSP;
    float s = 0.f;
    #pragma unroll 8
    for (int j = lane; j < NSP; j += 32) s += r[j];
    #pragma unroll
    for (int o = 16; o; o >>= 1) s += __shfl_xor_sync(0xffffffffu, s, o);
    if (lane == 0) g_spcl_invdeg[b * NSP + row] = rsqrtf(s);
}

// ---------------- generic fp32 GEMM: C = op(A[M,K] * opB(B)) -------------------
// flags: bit0 = relu, bit1 = B is [N,K] row-major (C = A @ B^T); else B is [K,N]
// symScale (len NSP per batch): A-tile *= sc[k], output *= sc[m]  (adj normalize)
#define TMI 64
#define TNI 64
#define TKI 16
#define SPAD 68
__global__ __launch_bounds__(256) void gemm_kernel(
    const float* __restrict__ A, int lda, size_t strideA,
    const float* __restrict__ B, int ldb, size_t strideB,
    float* __restrict__ C, int ldc, size_t strideC,
    int K,
    const float* __restrict__ bias,
    const float* __restrict__ symScale,
    int flags, float alpha)
{
    __shared__ float As[TKI][SPAD];
    __shared__ float Bs[TKI][SPAD];
    int b = blockIdx.z;
    A += (size_t)b * strideA;
    B += (size_t)b * strideB;
    C += (size_t)b * strideC;
    const float* sc = symScale ? symScale + (size_t)b * NSP : nullptr;
    int m0 = blockIdx.y * TMI, n0 = blockIdx.x * TNI;
    int tid = threadIdx.x;
    int tx = tid & 15, ty = tid >> 4;
    int la_r = tid >> 2, la_k = (tid & 3) * 4;
    float acc[4][4];
    #pragma unroll
    for (int i = 0; i < 4; i++)
        #pragma unroll
        for (int j = 0; j < 4; j++) acc[i][j] = 0.f;

    for (int k0 = 0; k0 < K; k0 += TKI) {
        float4 av = *(const float4*)(A + (size_t)(m0 + la_r) * lda + k0 + la_k);
        if (sc) {
            av.x *= sc[k0 + la_k + 0]; av.y *= sc[k0 + la_k + 1];
            av.z *= sc[k0 + la_k + 2]; av.w *= sc[k0 + la_k + 3];
        }
        As[la_k + 0][la_r] = av.x; As[la_k + 1][la_r] = av.y;
        As[la_k + 2][la_r] = av.z; As[la_k + 3][la_r] = av.w;
        if (flags & 2) {
            float4 bv = *(const float4*)(B + (size_t)(n0 + la_r) * ldb + k0 + la_k);
            Bs[la_k + 0][la_r] = bv.x; Bs[la_k + 1][la_r] = bv.y;
            Bs[la_k + 2][la_r] = bv.z; Bs[la_k + 3][la_r] = bv.w;
        } else {
            int r = tid >> 4;              // k
            int nn = (tid & 15) * 4;       // n
            float4 bv = *(const float4*)(B + (size_t)(k0 + r) * ldb + n0 + nn);
            *(float4*)&Bs[r][nn] = bv;
        }
        __syncthreads();
        #pragma unroll
        for (int kk = 0; kk < TKI; kk++) {
            float4 a  = *(const float4*)&As[kk][ty * 4];
            float4 bb = *(const float4*)&Bs[kk][tx * 4];
            float ar[4] = {a.x, a.y, a.z, a.w};
            float br[4] = {bb.x, bb.y, bb.z, bb.w};
            #pragma unroll
            for (int i = 0; i < 4; i++)
                #pragma unroll
                for (int j = 0; j < 4; j++) acc[i][j] += ar[i] * br[j];
        }
        __syncthreads();
    }
    int n = n0 + tx * 4;
    float bn[4] = {0.f, 0.f, 0.f, 0.f};
    if (bias) { bn[0] = bias[n]; bn[1] = bias[n + 1]; bn[2] = bias[n + 2]; bn[3] = bias[n + 3]; }
    #pragma unroll
    for (int i = 0; i < 4; i++) {
        int m = m0 + ty * 4 + i;
        float smv = (sc ? sc[m] : 1.f) * alpha;
        float4 o;
        o.x = acc[i][0] * smv + bn[0];
        o.y = acc[i][1] * smv + bn[1];
        o.z = acc[i][2] * smv + bn[2];
        o.w = acc[i][3] * smv + bn[3];
        if (flags & 1) {
            o.x = fmaxf(o.x, 0.f); o.y = fmaxf(o.y, 0.f);
            o.z = fmaxf(o.z, 0.f); o.w = fmaxf(o.w, 0.f);
        }
        *(float4*)(C + (size_t)m * ldc + n) = o;
    }
}

// ---------------- row-normalize z1, z2 (in place) ------------------------------
__global__ __launch_bounds__(256) void norm_kernel() {
    int b = blockIdx.y;
    int row = blockIdx.x * 8 + (threadIdx.x >> 5);
    int lane = threadIdx.x & 31;
    float* z1 = g_spcl_z1 + ((size_t)b * NSP + row) * ODIM;
    float* z2 = g_spcl_z2 + ((size_t)b * NSP + row) * ODIM;
    float a0 = z1[lane], a1 = z1[lane + 32];
    float ss = a0 * a0 + a1 * a1;
    #pragma unroll
    for (int o = 16; o; o >>= 1) ss += __shfl_xor_sync(0xffffffffu, ss, o);
    float inv = rsqrtf(ss);
    z1[lane] = a0 * inv; z1[lane + 32] = a1 * inv;
    float c0 = z2[lane], c1 = z2[lane + 32];
    float ss2 = c0 * c0 + c1 * c1;
    #pragma unroll
    for (int o = 16; o; o >>= 1) ss2 += __shfl_xor_sync(0xffffffffu, ss2, o);
    float inv2 = rsqrtf(ss2);
    z2[lane] = c0 * inv2; z2[lane + 32] = c1 * inv2;
}

// ---------------- per-row logsumexp + InfoNCE accumulation --------------------
__global__ __launch_bounds__(128) void lse_kernel(float* __restrict__ out) {
    int b = blockIdx.y;
    int row = blockIdx.x * 4 + (threadIdx.x >> 5);
    int lane = threadIdx.x & 31;
    const float* srow = g_spcl_sim + ((size_t)b * NSP + row) * NSP;
    float m = -1e30f, ssum = 0.f;
    #pragma unroll 4
    for (int j = lane; j < NSP; j += 32) {
        float v = srow[j];
        if (v > m) { ssum = ssum * __expf(m - v) + 1.f; m = v; }
        else       { ssum += __expf(v - m); }
    }
    #pragma unroll
    for (int o = 16; o; o >>= 1) {
        float m2 = __shfl_xor_sync(0xffffffffu, m, o);
        float s2 = __shfl_xor_sync(0xffffffffu, ssum, o);
        float mn = fmaxf(m, m2);
        ssum = ssum * __expf(m - mn) + s2 * __expf(m2 - mn);
        m = mn;
    }
    if (lane == 0) {
        float lse = m + logf(ssum);
        float loss = lse - srow[row];
        atomicAdd(out, loss * (1.0f / (NBATCH * NSP)));
    }
}

// ---------------- host launcher -----------------------------------------------
static float* spcl_devptr(const void* sym) {
    void* p = nullptr;
    cudaGetSymbolAddress(&p, sym);
    return (float*)p;
}

extern "C" void kernel_launch(void* const* d_in, const int* in_sizes, int n_in,
                              void* d_out, int out_size) {
    const float* features = (const float*)d_in[0];
    const int*   spidx    = (const int*)d_in[1];
    const float* W1  = (const float*)d_in[2];
    const float* b1  = (const float*)d_in[3];
    const float* W2  = (const float*)d_in[4];
    const float* b2  = (const float*)d_in[5];
    const float* Wp1 = (const float*)d_in[6];
    const float* bp1 = (const float*)d_in[7];
    const float* Wp2 = (const float*)d_in[8];
    const float* bp2 = (const float*)d_in[9];
    float* out = (float*)d_out;

    float* p_adj    = spcl_devptr(g_spcl_adj);
    float* p_invdeg = spcl_devptr(g_spcl_invdeg);
    float* p_spf    = spcl_devptr(g_spcl_spf);
    float* p_pT     = spcl_devptr(g_spcl_pT);
    float* p_h1     = spcl_devptr(g_spcl_h1);
    float* p_h2     = spcl_devptr(g_spcl_h2);
    float* p_z1     = spcl_devptr(g_spcl_z1);
    float* p_z2     = spcl_devptr(g_spcl_z2);
    float* p_sim    = spcl_devptr(g_spcl_sim);

    // 0) zero adj/cnt/out
    zero_kernel<<<4096, 256>>>(out);
    // 1) counts + binary adjacency (+eye)
    count_adj_kernel<<<dim3(HW / 256, NBATCH), 256>>>(spidx);
    // 2) scatter-mean aggregation (smem-privatized, partials)
    const int SC_SMEM = CG * NSP * 4 + 2048 * 2;   // 135168 B
    cudaFuncSetAttribute(scatter_kernel, cudaFuncAttributeMaxDynamicSharedMemorySize, SC_SMEM);
    scatter_kernel<<<dim3(NT_TILES, NCG, NBATCH), 256, SC_SMEM>>>(features, spidx);
    // 3) reduce partials -> spf[b][c][s]
    reduce_kernel<<<4096, 256>>>();
    // 4) invdeg
    invdeg_kernel<<<dim3(NSP / 8, NBATCH), 256>>>();
    // 5) GEMM1: pT[b][j][s] = W1 @ spf   (M=HID, N=NSP, K=NC, B N-mode)
    gemm_kernel<<<dim3(NSP / TNI, HID / TMI, NBATCH), 256>>>(
        W1, NC, 0, p_spf, NSP, (size_t)NC * NSP, p_pT, NSP, (size_t)HID * NSP,
        NC, nullptr, nullptr, 0, 1.f);
    // 6) GEMM2: h1 = relu(adj_norm @ p + b1)   (M=NSP, N=HID, K=NSP, B T-mode, sym scale)
    gemm_kernel<<<dim3(HID / TNI, NSP / TMI, NBATCH), 256>>>(
        p_adj, NSP, (size_t)NSP * NSP, p_pT, NSP, (size_t)HID * NSP, p_h1, HID,
        (size_t)NSP * HID, NSP, b1, p_invdeg, 3, 1.f);
    // 7) GEMM3: h2 = relu(h1 @ W2^T + b2)
    gemm_kernel<<<dim3(HID / TNI, NSP / TMI, NBATCH), 256>>>(
        p_h1, HID, (size_t)NSP * HID, W2, HID, 0, p_h2, HID, (size_t)NSP * HID,
        HID, b2, nullptr, 3, 1.f);
    // 8) GEMM4: z1 = h2 @ Wp1^T + bp1 ; z2 = h2 @ Wp2^T + bp2
    gemm_kernel<<<dim3(ODIM / TNI, NSP / TMI, NBATCH), 256>>>(
        p_h2, HID, (size_t)NSP * HID, Wp1, HID, 0, p_z1, ODIM, (size_t)NSP * ODIM,
        HID, bp1, nullptr, 2, 1.f);
    gemm_kernel<<<dim3(ODIM / TNI, NSP / TMI, NBATCH), 256>>>(
        p_h2, HID, (size_t)NSP * HID, Wp2, HID, 0, p_z2, ODIM, (size_t)NSP * ODIM,
        HID, bp2, nullptr, 2, 1.f);
    // 9) row-normalize
    norm_kernel<<<dim3(NSP / 8, NBATCH), 256>>>();
    // 10) GEMM5: sim = (z1n @ z2n^T) / T
    gemm_kernel<<<dim3(NSP / TNI, NSP / TMI, NBATCH), 256>>>(
        p_z1, ODIM, (size_t)NSP * ODIM, p_z2, ODIM, (size_t)NSP * ODIM, p_sim, NSP,
        (size_t)NSP * NSP, ODIM, nullptr, nullptr, 2, INV_T);
    // 11) logsumexp + loss accumulation
    lse_kernel<<<dim3(NSP / 4, NBATCH), 128>>>(out);
}

// round 2
// speedup vs baseline: 1.9198x; 1.9198x over previous
#include <cuda_runtime.h>
#include <math.h>

#define NBATCH 4
#define NC     256
#define HW     65536
#define WIMG   256
#define NSP    1024
#define HID    128
#define ODIM   64
#define INV_T  10.0f

// ---------------- scratch (device globals; no allocation allowed) ----------------
__device__ float g_spcl_cnt[NBATCH * NSP];
__device__ int   g_spcl_off[NBATCH * NSP];
__device__ int   g_spcl_fill[NBATCH * NSP];
__device__ int   g_spcl_slot[(size_t)NBATCH * HW];
__device__ float g_spcl_adj[(size_t)NBATCH * NSP * NSP];              // 16 MB
__device__ float g_spcl_invdeg[NBATCH * NSP];
__device__ float g_spcl_featT[(size_t)NBATCH * HW * NC];              // 256 MB, sorted rows
__device__ float g_spcl_spf[(size_t)NBATCH * NSP * NC];               // [b][s][c]
__device__ float g_spcl_p[(size_t)NBATCH * NSP * HID];                // [b][s][j]
__device__ float g_spcl_h1[(size_t)NBATCH * NSP * HID];
__device__ float g_spcl_h2[(size_t)NBATCH * NSP * HID];
__device__ float g_spcl_z1[(size_t)NBATCH * NSP * ODIM];
__device__ float g_spcl_z2[(size_t)NBATCH * NSP * ODIM];
__device__ float g_spcl_sim[(size_t)NBATCH * NSP * NSP];              // 16 MB

// ---------------- zero: adj + cnt + fill + out --------------------------------
__global__ __launch_bounds__(256) void zero_kernel(float* d_out) {
    size_t gid = (size_t)blockIdx.x * 256 + threadIdx.x;   // 4096*256 = 1,048,576
    float4 z = make_float4(0.f, 0.f, 0.f, 0.f);
    *(float4*)(g_spcl_adj + gid * 4) = z;
    if (gid < (NBATCH * NSP) / 4) {
        *(float4*)(g_spcl_cnt + gid * 4) = z;
        ((int4*)g_spcl_fill)[gid] = make_int4(0, 0, 0, 0);
    }
    if (gid == 0) d_out[0] = 0.f;
}

// ---------------- counts + binary adjacency ----------------------------------
__global__ __launch_bounds__(256) void count_adj_kernel(const int* __restrict__ idx) {
    int b = blockIdx.y;
    int p = blockIdx.x * 256 + threadIdx.x;
    const int* ib = idx + (size_t)b * HW;
    int s = ib[p];
    atomicAdd(&g_spcl_cnt[b * NSP + s], 1.0f);
    float* adjb = g_spcl_adj + (size_t)b * NSP * NSP;
    if ((p & (WIMG - 1)) < WIMG - 1) {          // right neighbor
        int s2 = ib[p + 1];
        if (s2 != s) { adjb[(size_t)s * NSP + s2] = 1.f; adjb[(size_t)s2 * NSP + s] = 1.f; }
    }
    if (p < HW - WIMG) {                        // down neighbor
        int s2 = ib[p + WIMG];
        if (s2 != s) { adjb[(size_t)s * NSP + s2] = 1.f; adjb[(size_t)s2 * NSP + s] = 1.f; }
    }
    if (p < NSP) adjb[(size_t)p * NSP + p] = 1.f;   // eye
}

// ---------------- exclusive scan of counts -> offsets (1 block per batch) -----
__global__ __launch_bounds__(1024) void scan_kernel() {
    __shared__ int sm[NSP];
    int b = blockIdx.x;
    int t = threadIdx.x;
    int v = (int)g_spcl_cnt[b * NSP + t];
    sm[t] = v;
    __syncthreads();
    for (int o = 1; o < NSP; o <<= 1) {
        int x = (t >= o) ? sm[t - o] : 0;
        __syncthreads();
        sm[t] += x;
        __syncthreads();
    }
    g_spcl_off[b * NSP + t] = sm[t] - v;   // exclusive
}

// ---------------- binning: pixel -> sorted slot --------------------------------
__global__ __launch_bounds__(256) void bin_kernel(const int* __restrict__ idx) {
    int b = blockIdx.y;
    int p = blockIdx.x * 256 + threadIdx.x;
    int s = idx[(size_t)b * HW + p];
    int slot = g_spcl_off[b * NSP + s] + atomicAdd(&g_spcl_fill[b * NSP + s], 1);
    g_spcl_slot[(size_t)b * HW + p] = slot;
}

// ---------------- scatter-transpose: feat [C,HW] -> featT [slot,C] -------------
// grid (HW/64, NC/32, NBATCH), 256 threads
__global__ __launch_bounds__(256) void transpose_kernel(const float* __restrict__ feat) {
    __shared__ float tile[32][65];
    __shared__ int sl[64];
    int b = blockIdx.z, c0 = blockIdx.y * 32, p0 = blockIdx.x * 64;
    int tid = threadIdx.x;
    if (tid < 64) sl[tid] = g_spcl_slot[(size_t)b * HW + p0 + tid];
    int px = tid & 63, cl = tid >> 6;
    const float* f = feat + ((size_t)b * NC + c0) * HW + p0;
    #pragma unroll
    for (int i = 0; i < 8; i++)
        tile[cl + i * 4][px] = f[(size_t)(cl + i * 4) * HW + px];
    __syncthreads();
    int w = tid >> 5, lane = tid & 31;
    #pragma unroll
    for (int i = 0; i < 8; i++) {
        int p = w + i * 8;
        g_spcl_featT[((size_t)b * HW + sl[p]) * NC + c0 + lane] = tile[lane][p];
    }
}

// ---------------- contiguous segment mean: featT -> spf [b][s][c] --------------
__global__ __launch_bounds__(256) void segsum_kernel() {
    int s = blockIdx.x, b = blockIdx.y, c = threadIdx.x;
    int start = g_spcl_off[b * NSP + s];
    int n = (int)g_spcl_cnt[b * NSP + s];
    const float* base = g_spcl_featT + ((size_t)b * HW + start) * NC + c;
    float a0 = 0.f, a1 = 0.f, a2 = 0.f, a3 = 0.f;
    int r = 0;
    for (; r + 4 <= n; r += 4) {
        a0 += base[(size_t)r * NC];
        a1 += base[(size_t)(r + 1) * NC];
        a2 += base[(size_t)(r + 2) * NC];
        a3 += base[(size_t)(r + 3) * NC];
    }
    for (; r < n; r++) a0 += base[(size_t)r * NC];
    float acc = (a0 + a1) + (a2 + a3);
    g_spcl_spf[((size_t)b * NSP + s) * NC + c] = (n > 0) ? acc / (float)n : 0.f;
}

// ---------------- invdeg = rsqrt(rowsum(adj)) ---------------------------------
__global__ __launch_bounds__(256) void invdeg_kernel() {
    int b = blockIdx.y;
    int row = blockIdx.x * 8 + (threadIdx.x >> 5);
    int lane = threadIdx.x & 31;
    const float* r = g_spcl_adj + ((size_t)b * NSP + row) * NSP;
    float s = 0.f;
    #pragma unroll 8
    for (int j = lane; j < NSP; j += 32) s += r[j];
    #pragma unroll
    for (int o = 16; o; o >>= 1) s += __shfl_xor_sync(0xffffffffu, s, o);
    if (lane == 0) g_spcl_invdeg[b * NSP + row] = rsqrtf(s);
}

// ---------------- generic fp32 GEMM: C = op(A[M,K] * opB(B)) -------------------
// flags: bit0 = relu, bit1 = B is [N,K] row-major (C = A @ B^T); else B is [K,N]
// symScale (len NSP per batch): A-tile *= sc[k], output *= sc[m]  (adj normalize)
#define TMI 64
#define TNI 64
#define TKI 16
#define SPAD 68
__global__ __launch_bounds__(256) void gemm_kernel(
    const float* __restrict__ A, int lda, size_t strideA,
    const float* __restrict__ B, int ldb, size_t strideB,
    float* __restrict__ C, int ldc, size_t strideC,
    int K,
    const float* __restrict__ bias,
    const float* __restrict__ symScale,
    int flags, float alpha)
{
    __shared__ float As[TKI][SPAD];
    __shared__ float Bs[TKI][SPAD];
    int b = blockIdx.z;
    A += (size_t)b * strideA;
    B += (size_t)b * strideB;
    C += (size_t)b * strideC;
    const float* sc = symScale ? symScale + (size_t)b * NSP : nullptr;
    int m0 = blockIdx.y * TMI, n0 = blockIdx.x * TNI;
    int tid = threadIdx.x;
    int tx = tid & 15, ty = tid >> 4;
    int la_r = tid >> 2, la_k = (tid & 3) * 4;
    float acc[4][4];
    #pragma unroll
    for (int i = 0; i < 4; i++)
        #pragma unroll
        for (int j = 0; j < 4; j++) acc[i][j] = 0.f;

    for (int k0 = 0; k0 < K; k0 += TKI) {
        float4 av = *(const float4*)(A + (size_t)(m0 + la_r) * lda + k0 + la_k);
        if (sc) {
            av.x *= sc[k0 + la_k + 0]; av.y *= sc[k0 + la_k + 1];
            av.z *= sc[k0 + la_k + 2]; av.w *= sc[k0 + la_k + 3];
        }
        As[la_k + 0][la_r] = av.x; As[la_k + 1][la_r] = av.y;
        As[la_k + 2][la_r] = av.z; As[la_k + 3][la_r] = av.w;
        if (flags & 2) {
            float4 bv = *(const float4*)(B + (size_t)(n0 + la_r) * ldb + k0 + la_k);
            Bs[la_k + 0][la_r] = bv.x; Bs[la_k + 1][la_r] = bv.y;
            Bs[la_k + 2][la_r] = bv.z; Bs[la_k + 3][la_r] = bv.w;
        } else {
            int r = tid >> 4;              // k
            int nn = (tid & 15) * 4;       // n
            float4 bv = *(const float4*)(B + (size_t)(k0 + r) * ldb + n0 + nn);
            *(float4*)&Bs[r][nn] = bv;
        }
        __syncthreads();
        #pragma unroll
        for (int kk = 0; kk < TKI; kk++) {
            float4 a  = *(const float4*)&As[kk][ty * 4];
            float4 bb = *(const float4*)&Bs[kk][tx * 4];
            float ar[4] = {a.x, a.y, a.z, a.w};
            float br[4] = {bb.x, bb.y, bb.z, bb.w};
            #pragma unroll
            for (int i = 0; i < 4; i++)
                #pragma unroll
                for (int j = 0; j < 4; j++) acc[i][j] += ar[i] * br[j];
        }
        __syncthreads();
    }
    int n = n0 + tx * 4;
    float bn[4] = {0.f, 0.f, 0.f, 0.f};
    if (bias) { bn[0] = bias[n]; bn[1] = bias[n + 1]; bn[2] = bias[n + 2]; bn[3] = bias[n + 3]; }
    #pragma unroll
    for (int i = 0; i < 4; i++) {
        int m = m0 + ty * 4 + i;
        float smv = (sc ? sc[m] : 1.f) * alpha;
        float4 o;
        o.x = acc[i][0] * smv + bn[0];
        o.y = acc[i][1] * smv + bn[1];
        o.z = acc[i][2] * smv + bn[2];
        o.w = acc[i][3] * smv + bn[3];
        if (flags & 1) {
            o.x = fmaxf(o.x, 0.f); o.y = fmaxf(o.y, 0.f);
            o.z = fmaxf(o.z, 0.f); o.w = fmaxf(o.w, 0.f);
        }
        *(float4*)(C + (size_t)m * ldc + n) = o;
    }
}

// ---------------- row-normalize z1, z2 (in place) ------------------------------
__global__ __launch_bounds__(256) void norm_kernel() {
    int b = blockIdx.y;
    int row = blockIdx.x * 8 + (threadIdx.x >> 5);
    int lane = threadIdx.x & 31;
    float* z1 = g_spcl_z1 + ((size_t)b * NSP + row) * ODIM;
    float* z2 = g_spcl_z2 + ((size_t)b * NSP + row) * ODIM;
    float a0 = z1[lane], a1 = z1[lane + 32];
    float ss = a0 * a0 + a1 * a1;
    #pragma unroll
    for (int o = 16; o; o >>= 1) ss += __shfl_xor_sync(0xffffffffu, ss, o);
    float inv = rsqrtf(ss);
    z1[lane] = a0 * inv; z1[lane + 32] = a1 * inv;
    float c0 = z2[lane], c1 = z2[lane + 32];
    float ss2 = c0 * c0 + c1 * c1;
    #pragma unroll
    for (int o = 16; o; o >>= 1) ss2 += __shfl_xor_sync(0xffffffffu, ss2, o);
    float inv2 = rsqrtf(ss2);
    z2[lane] = c0 * inv2; z2[lane + 32] = c1 * inv2;
}

// ---------------- per-row logsumexp + InfoNCE accumulation --------------------
__global__ __launch_bounds__(128) void lse_kernel(float* __restrict__ out) {
    int b = blockIdx.y;
    int row = blockIdx.x * 4 + (threadIdx.x >> 5);
    int lane = threadIdx.x & 31;
    const float* srow = g_spcl_sim + ((size_t)b * NSP + row) * NSP;
    float m = -1e30f, ssum = 0.f;
    #pragma unroll 4
    for (int j = lane; j < NSP; j += 32) {
        float v = srow[j];
        if (v > m) { ssum = ssum * __expf(m - v) + 1.f; m = v; }
        else       { ssum += __expf(v - m); }
    }
    #pragma unroll
    for (int o = 16; o; o >>= 1) {
        float m2 = __shfl_xor_sync(0xffffffffu, m, o);
        float s2 = __shfl_xor_sync(0xffffffffu, ssum, o);
        float mn = fmaxf(m, m2);
        ssum = ssum * __expf(m - mn) + s2 * __expf(m2 - mn);
        m = mn;
    }
    if (lane == 0) {
        float lse = m + logf(ssum);
        float loss = lse - srow[row];
        atomicAdd(out, loss * (1.0f / (NBATCH * NSP)));
    }
}

// ---------------- host launcher -----------------------------------------------
static float* spcl_devptr(const void* sym) {
    void* p = nullptr;
    cudaGetSymbolAddress(&p, sym);
    return (float*)p;
}

extern "C" void kernel_launch(void* const* d_in, const int* in_sizes, int n_in,
                              void* d_out, int out_size) {
    const float* features = (const float*)d_in[0];
    const int*   spidx    = (const int*)d_in[1];
    const float* W1  = (const float*)d_in[2];
    const float* b1  = (const float*)d_in[3];
    const float* W2  = (const float*)d_in[4];
    const float* b2  = (const float*)d_in[5];
    const float* Wp1 = (const float*)d_in[6];
    const float* bp1 = (const float*)d_in[7];
    const float* Wp2 = (const float*)d_in[8];
    const float* bp2 = (const float*)d_in[9];
    float* out = (float*)d_out;

    float* p_adj    = spcl_devptr(g_spcl_adj);
    float* p_invdeg = spcl_devptr(g_spcl_invdeg);
    float* p_spf    = spcl_devptr(g_spcl_spf);
    float* p_p      = spcl_devptr(g_spcl_p);
    float* p_h1     = spcl_devptr(g_spcl_h1);
    float* p_h2     = spcl_devptr(g_spcl_h2);
    float* p_z1     = spcl_devptr(g_spcl_z1);
    float* p_z2     = spcl_devptr(g_spcl_z2);
    float* p_sim    = spcl_devptr(g_spcl_sim);

    // 0) zero adj/cnt/fill/out
    zero_kernel<<<4096, 256>>>(out);
    // 1) counts + binary adjacency (+eye)
    count_adj_kernel<<<dim3(HW / 256, NBATCH), 256>>>(spidx);
    // 2) offsets per batch
    scan_kernel<<<NBATCH, 1024>>>();
    // 3) bin pixels into sorted slots
    bin_kernel<<<dim3(HW / 256, NBATCH), 256>>>(spidx);
    // 4) scatter-transpose features into sorted rows
    transpose_kernel<<<dim3(HW / 64, NC / 32, NBATCH), 256>>>(features);
    // 5) contiguous segment mean -> spf [b][s][c]
    segsum_kernel<<<dim3(NSP, NBATCH), 256>>>();
    // 6) invdeg
    invdeg_kernel<<<dim3(NSP / 8, NBATCH), 256>>>();
    // 7) GEMM1: p = spf @ W1^T   (M=NSP, N=HID, K=NC, B T-mode)
    gemm_kernel<<<dim3(HID / TNI, NSP / TMI, NBATCH), 256>>>(
        p_spf, NC, (size_t)NSP * NC, W1, NC, 0, p_p, HID, (size_t)NSP * HID,
        NC, nullptr, nullptr, 2, 1.f);
    // 8) GEMM2: h1 = relu(adj_norm @ p + b1)   (M=NSP, N=HID, K=NSP, B N-mode, sym scale)
    gemm_kernel<<<dim3(HID / TNI, NSP / TMI, NBATCH), 256>>>(
        p_adj, NSP, (size_t)NSP * NSP, p_p, HID, (size_t)NSP * HID, p_h1, HID,
        (size_t)NSP * HID, NSP, b1, p_invdeg, 1, 1.f);
    // 9) GEMM3: h2 = relu(h1 @ W2^T + b2)
    gemm_kernel<<<dim3(HID / TNI, NSP / TMI, NBATCH), 256>>>(
        p_h1, HID, (size_t)NSP * HID, W2, HID, 0, p_h2, HID, (size_t)NSP * HID,
        HID, b2, nullptr, 3, 1.f);
    // 10) GEMM4: z1 = h2 @ Wp1^T + bp1 ; z2 = h2 @ Wp2^T + bp2
    gemm_kernel<<<dim3(ODIM / TNI, NSP / TMI, NBATCH), 256>>>(
        p_h2, HID, (size_t)NSP * HID, Wp1, HID, 0, p_z1, ODIM, (size_t)NSP * ODIM,
        HID, bp1, nullptr, 2, 1.f);
    gemm_kernel<<<dim3(ODIM / TNI, NSP / TMI, NBATCH), 256>>>(
        p_h2, HID, (size_t)NSP * HID, Wp2, HID, 0, p_z2, ODIM, (size_t)NSP * ODIM,
        HID, bp2, nullptr, 2, 1.f);
    // 11) row-normalize
    norm_kernel<<<dim3(NSP / 8, NBATCH), 256>>>();
    // 12) GEMM5: sim = (z1n @ z2n^T) / T
    gemm_kernel<<<dim3(NSP / TNI, NSP / TMI, NBATCH), 256>>>(
        p_z1, ODIM, (size_t)NSP * ODIM, p_z2, ODIM, (size_t)NSP * ODIM, p_sim, NSP,
        (size_t)NSP * NSP, ODIM, nullptr, nullptr, 2, INV_T);
    // 13) logsumexp + loss accumulation
    lse_kernel<<<dim3(NSP / 4, NBATCH), 128>>>(out);
}

// round 4
// speedup vs baseline: 2.0182x; 1.0513x over previous
#include <cuda_runtime.h>
#include <cuda_fp16.h>
#include <math.h>

#define NBATCH 4
#define NC     256
#define HW     65536
#define WIMG   256
#define NSP    1024
#define HID    128
#define ODIM   64
#define INV_T  10.0f

// ---------------- scratch (device globals; no allocation allowed) ----------------
__device__ int    g_spcl_cnti[NBATCH * NSP];
__device__ int    g_spcl_off[NBATCH * NSP];
__device__ int    g_spcl_rank[(size_t)NBATCH * HW];                    // 1 MB
__device__ unsigned char g_spcl_adj[(size_t)NBATCH * NSP * NSP];       // 4 MB
__device__ float  g_spcl_invdeg[NBATCH * NSP];
__device__ __half g_spcl_featT16[(size_t)HW * NC];                     // 32 MB, ONE batch at a time
__device__ float  g_spcl_spf[(size_t)NBATCH * NSP * NC];               // [b][s][c]
__device__ float  g_spcl_p[(size_t)NBATCH * NSP * HID];
__device__ float  g_spcl_h1[(size_t)NBATCH * NSP * HID];
__device__ float  g_spcl_h2[(size_t)NBATCH * NSP * HID];
__device__ float  g_spcl_z1[(size_t)NBATCH * NSP * ODIM];
__device__ float  g_spcl_z2[(size_t)NBATCH * NSP * ODIM];
__device__ float  g_spcl_diag[NBATCH * NSP];

// ---------------- zero: adj(bytes) + cnti + out --------------------------------
__global__ __launch_bounds__(256) void zero_kernel(float* d_out) {
    size_t gid = (size_t)blockIdx.x * 256 + threadIdx.x;   // 2048*256 = 524288, 8B each
    ((uint2*)g_spcl_adj)[gid] = make_uint2(0u, 0u);
    if (gid < (NBATCH * NSP) / 4) ((int4*)g_spcl_cnti)[gid] = make_int4(0, 0, 0, 0);
    if (gid == 0) d_out[0] = 0.f;
}

// ---------------- counts (+rank) + binary adjacency ----------------------------
__global__ __launch_bounds__(256) void count_adj_kernel(const int* __restrict__ idx) {
    int b = blockIdx.y;
    int p = blockIdx.x * 256 + threadIdx.x;
    const int* ib = idx + (size_t)b * HW;
    int s = ib[p];
    int r = atomicAdd(&g_spcl_cnti[b * NSP + s], 1);
    g_spcl_rank[(size_t)b * HW + p] = r;
    unsigned char* adjb = g_spcl_adj + (size_t)b * NSP * NSP;
    if ((p & (WIMG - 1)) < WIMG - 1) {          // right neighbor
        int s2 = ib[p + 1];
        if (s2 != s) { adjb[(size_t)s * NSP + s2] = 1; adjb[(size_t)s2 * NSP + s] = 1; }
    }
    if (p < HW - WIMG) {                        // down neighbor
        int s2 = ib[p + WIMG];
        if (s2 != s) { adjb[(size_t)s * NSP + s2] = 1; adjb[(size_t)s2 * NSP + s] = 1; }
    }
    if (p < NSP) adjb[(size_t)p * NSP + p] = 1;   // eye
}

// ---------------- exclusive scan of counts -> offsets (1 block per batch) -----
__global__ __launch_bounds__(1024) void scan_kernel() {
    __shared__ int sm[NSP];
    int b = blockIdx.x;
    int t = threadIdx.x;
    int v = g_spcl_cnti[b * NSP + t];
    sm[t] = v;
    __syncthreads();
    for (int o = 1; o < NSP; o <<= 1) {
        int x = (t >= o) ? sm[t - o] : 0;
        __syncthreads();
        sm[t] += x;
        __syncthreads();
    }
    g_spcl_off[b * NSP + t] = sm[t] - v;   // exclusive
}

// ---------------- invdeg = rsqrt(rowsum(adj)) via dp4a -------------------------
__global__ __launch_bounds__(256) void invdeg_kernel() {
    int b = blockIdx.y;
    int row = blockIdx.x * 8 + (threadIdx.x >> 5);
    int lane = threadIdx.x & 31;
    const uint4* r = (const uint4*)(g_spcl_adj + ((size_t)b * NSP + row) * NSP);
    uint4 v1 = r[lane], v2 = r[lane + 32];
    unsigned int s = 0u;
    s = __dp4a(v1.x, 0x01010101u, s); s = __dp4a(v1.y, 0x01010101u, s);
    s = __dp4a(v1.z, 0x01010101u, s); s = __dp4a(v1.w, 0x01010101u, s);
    s = __dp4a(v2.x, 0x01010101u, s); s = __dp4a(v2.y, 0x01010101u, s);
    s = __dp4a(v2.z, 0x01010101u, s); s = __dp4a(v2.w, 0x01010101u, s);
    int si = (int)s;
    #pragma unroll
    for (int o = 16; o; o >>= 1) si += __shfl_xor_sync(0xffffffffu, si, o);
    if (lane == 0) g_spcl_invdeg[b * NSP + row] = rsqrtf((float)si);
}

// ---------------- scatter-transpose: feat [C,HW] -> featT16 [slot][C] ----------
// grid (HW/64, NC/64), 256 threads; one batch per launch
__global__ __launch_bounds__(256) void transpose_kernel(const float* __restrict__ feat,
                                                        const int* __restrict__ idx, int b) {
    __shared__ float tile[64][65];
    __shared__ int sl[64];
    int c0 = blockIdx.y * 64, p0 = blockIdx.x * 64;
    int tid = threadIdx.x;
    if (tid < 64) {
        int p = p0 + tid;
        int s = idx[(size_t)b * HW + p];
        sl[tid] = g_spcl_off[b * NSP + s] + g_spcl_rank[(size_t)b * HW + p];
    }
    int px = tid & 63, cl = tid >> 6;
    const float* f = feat + ((size_t)b * NC + c0) * HW + p0;
    #pragma unroll
    for (int i = 0; i < 16; i++)
        tile[cl + i * 4][px] = f[(size_t)(cl + i * 4) * HW + px];
    __syncthreads();
    int w = tid >> 5, lane = tid & 31;
    __half2* dst = (__half2*)g_spcl_featT16;
    #pragma unroll
    for (int i = 0; i < 8; i++) {
        int p = w + i * 8;
        dst[(size_t)sl[p] * (NC / 2) + (c0 >> 1) + lane] =
            __floats2half2_rn(tile[lane * 2][p], tile[lane * 2 + 1][p]);
    }
}

// ---------------- contiguous segment mean: featT16 -> spf [b][s][c] ------------
__global__ __launch_bounds__(128) void segsum_kernel(int b) {
    int s = blockIdx.x, t = threadIdx.x;
    int start = g_spcl_off[b * NSP + s];
    int n = g_spcl_cnti[b * NSP + s];
    const __half2* base = (const __half2*)g_spcl_featT16 + (size_t)start * (NC / 2) + t;
    float2 a0 = make_float2(0.f, 0.f), a1 = make_float2(0.f, 0.f);
    int r = 0;
    for (; r + 2 <= n; r += 2) {
        float2 x0 = __half22float2(base[(size_t)r * (NC / 2)]);
        float2 x1 = __half22float2(base[(size_t)(r + 1) * (NC / 2)]);
        a0.x += x0.x; a0.y += x0.y; a1.x += x1.x; a1.y += x1.y;
    }
    if (r < n) {
        float2 x0 = __half22float2(base[(size_t)r * (NC / 2)]);
        a0.x += x0.x; a0.y += x0.y;
    }
    float invn = (n > 0) ? 1.f / (float)n : 0.f;
    float2 o = make_float2((a0.x + a1.x) * invn, (a0.y + a1.y) * invn);
    *(float2*)(g_spcl_spf + ((size_t)b * NSP + s) * NC + 2 * t) = o;
}

// ---------------- generic fp32 GEMM: C = op(A[M,K] * opB(B)) -------------------
// flags: bit0 relu; bit1 B is [N,K] (C=A@B^T); bit2 A is uint8 (adjacency)
// symScale: A *= sc[k] (on load), out *= sc[m]
#define TMI 64
#define TNI 64
#define TKI 16
#define SPAD 68
__global__ __launch_bounds__(256) void gemm_kernel(
    const void* __restrict__ Av, int lda, size_t strideA,
    const float* __restrict__ B, int ldb, size_t strideB,
    float* __restrict__ C, int ldc, size_t strideC,
    int K,
    const float* __restrict__ bias,
    const float* __restrict__ symScale,
    int flags, float alpha)
{
    __shared__ float As[TKI][SPAD];
    __shared__ float Bs[TKI][SPAD];
    int b = blockIdx.z;
    const float* A = nullptr;
    const unsigned char* A8 = nullptr;
    if (flags & 4) A8 = (const unsigned char*)Av + (size_t)b * strideA;
    else           A  = (const float*)Av + (size_t)b * strideA;
    B += (size_t)b * strideB;
    C += (size_t)b * strideC;
    const float* sc = symScale ? symScale + (size_t)b * NSP : nullptr;
    int m0 = blockIdx.y * TMI, n0 = blockIdx.x * TNI;
    int tid = threadIdx.x;
    int tx = tid & 15, ty = tid >> 4;
    int la_r = tid >> 2, la_k = (tid & 3) * 4;
    float acc[4][4];
    #pragma unroll
    for (int i = 0; i < 4; i++)
        #pragma unroll
        for (int j = 0; j < 4; j++) acc[i][j] = 0.f;

    for (int k0 = 0; k0 < K; k0 += TKI) {
        if (flags & 4) {
            unsigned int v = *(const unsigned int*)(A8 + (size_t)(m0 + la_r) * lda + k0 + la_k);
            As[la_k + 0][la_r] = (float)(v & 0xffu)        * sc[k0 + la_k + 0];
            As[la_k + 1][la_r] = (float)((v >> 8) & 0xffu) * sc[k0 + la_k + 1];
            As[la_k + 2][la_r] = (float)((v >> 16) & 0xffu)* sc[k0 + la_k + 2];
            As[la_k + 3][la_r] = (float)(v >> 24)          * sc[k0 + la_k + 3];
        } else {
            float4 av = *(const float4*)(A + (size_t)(m0 + la_r) * lda + k0 + la_k);
            As[la_k + 0][la_r] = av.x; As[la_k + 1][la_r] = av.y;
            As[la_k + 2][la_r] = av.z; As[la_k + 3][la_r] = av.w;
        }
        if (flags & 2) {
            float4 bv = *(const float4*)(B + (size_t)(n0 + la_r) * ldb + k0 + la_k);
            Bs[la_k + 0][la_r] = bv.x; Bs[la_k + 1][la_r] = bv.y;
            Bs[la_k + 2][la_r] = bv.z; Bs[la_k + 3][la_r] = bv.w;
        } else {
            int r = tid >> 4;              // k
            int nn = (tid & 15) * 4;       // n
            float4 bv = *(const float4*)(B + (size_t)(k0 + r) * ldb + n0 + nn);
            *(float4*)&Bs[r][nn] = bv;
        }
        __syncthreads();
        #pragma unroll
        for (int kk = 0; kk < TKI; kk++) {
            float4 a  = *(const float4*)&As[kk][ty * 4];
            float4 bb = *(const float4*)&Bs[kk][tx * 4];
            float ar[4] = {a.x, a.y, a.z, a.w};
            float br[4] = {bb.x, bb.y, bb.z, bb.w};
            #pragma unroll
            for (int i = 0; i < 4; i++)
                #pragma unroll
                for (int j = 0; j < 4; j++) acc[i][j] += ar[i] * br[j];
        }
        __syncthreads();
    }
    int n = n0 + tx * 4;
    float bn[4] = {0.f, 0.f, 0.f, 0.f};
    if (bias) { bn[0] = bias[n]; bn[1] = bias[n + 1]; bn[2] = bias[n + 2]; bn[3] = bias[n + 3]; }
    #pragma unroll
    for (int i = 0; i < 4; i++) {
        int m = m0 + ty * 4 + i;
        float smv = (sc ? sc[m] : 1.f) * alpha;
        float4 o;
        o.x = acc[i][0] * smv + bn[0];
        o.y = acc[i][1] * smv + bn[1];
        o.z = acc[i][2] * smv + bn[2];
        o.w = acc[i][3] * smv + bn[3];
        if (flags & 1) {
            o.x = fmaxf(o.x, 0.f); o.y = fmaxf(o.y, 0.f);
            o.z = fmaxf(o.z, 0.f); o.w = fmaxf(o.w, 0.f);
        }
        *(float4*)(C + (size_t)m * ldc + n) = o;
    }
}

// ---------------- row-normalize z1, z2 (in place) + diag ------------------------
__global__ __launch_bounds__(256) void norm_kernel() {
    int b = blockIdx.y;
    int row = blockIdx.x * 8 + (threadIdx.x >> 5);
    int lane = threadIdx.x & 31;
    float* z1 = g_spcl_z1 + ((size_t)b * NSP + row) * ODIM;
    float* z2 = g_spcl_z2 + ((size_t)b * NSP + row) * ODIM;
    float a0 = z1[lane], a1 = z1[lane + 32];
    float ss = a0 * a0 + a1 * a1;
    #pragma unroll
    for (int o = 16; o; o >>= 1) ss += __shfl_xor_sync(0xffffffffu, ss, o);
    float inv = rsqrtf(ss);
    float a0n = a0 * inv, a1n = a1 * inv;
    z1[lane] = a0n; z1[lane + 32] = a1n;
    float c0 = z2[lane], c1 = z2[lane + 32];
    float ss2 = c0 * c0 + c1 * c1;
    #pragma unroll
    for (int o = 16; o; o >>= 1) ss2 += __shfl_xor_sync(0xffffffffu, ss2, o);
    float inv2 = rsqrtf(ss2);
    float c0n = c0 * inv2, c1n = c1 * inv2;
    z2[lane] = c0n; z2[lane + 32] = c1n;
    float dd = a0n * c0n + a1n * c1n;
    #pragma unroll
    for (int o = 16; o; o >>= 1) dd += __shfl_xor_sync(0xffffffffu, dd, o);
    if (lane == 0) g_spcl_diag[b * NSP + row] = dd * INV_T;
}

// ---------------- fused sim GEMM + online logsumexp + loss ---------------------
// grid (NSP/32, NBATCH), 256 threads: warp ty handles rows m0+ty*4..+3
__global__ __launch_bounds__(256) void simlse_kernel(float* __restrict__ out) {
    __shared__ float As[ODIM][36];   // [k][m], m-tile 32
    __shared__ float Bs[ODIM][66];   // [k][n], n-chunk 64
    __shared__ float sloss[32];
    int b = blockIdx.y;
    int m0 = blockIdx.x * 32;
    int tid = threadIdx.x;
    int tx = tid & 31, ty = tid >> 5;
    const float* z1 = g_spcl_z1 + (size_t)b * NSP * ODIM;
    const float* z2 = g_spcl_z2 + (size_t)b * NSP * ODIM;
    {
        int r = tid >> 3, cg = (tid & 7) * 8;
        float4 v1 = *(const float4*)(z1 + (size_t)(m0 + r) * ODIM + cg);
        float4 v2 = *(const float4*)(z1 + (size_t)(m0 + r) * ODIM + cg + 4);
        As[cg + 0][r] = v1.x; As[cg + 1][r] = v1.y; As[cg + 2][r] = v1.z; As[cg + 3][r] = v1.w;
        As[cg + 4][r] = v2.x; As[cg + 5][r] = v2.y; As[cg + 6][r] = v2.z; As[cg + 7][r] = v2.w;
    }
    float mrun[4], srun[4];
    #pragma unroll
    for (int i = 0; i < 4; i++) { mrun[i] = -1e30f; srun[i] = 0.f; }

    for (int n0 = 0; n0 < NSP; n0 += 64) {
        __syncthreads();
        {
            int r = tid >> 2, cg = (tid & 3) * 16;
            #pragma unroll
            for (int q = 0; q < 4; q++) {
                float4 v = *(const float4*)(z2 + (size_t)(n0 + r) * ODIM + cg + q * 4);
                Bs[cg + q * 4 + 0][r] = v.x; Bs[cg + q * 4 + 1][r] = v.y;
                Bs[cg + q * 4 + 2][r] = v.z; Bs[cg + q * 4 + 3][r] = v.w;
            }
        }
        __syncthreads();
        float acc[4][2];
        #pragma unroll
        for (int i = 0; i < 4; i++) { acc[i][0] = 0.f; acc[i][1] = 0.f; }
        #pragma unroll
        for (int kk = 0; kk < ODIM; kk++) {
            float4 a = *(const float4*)&As[kk][ty * 4];
            float2 bb = *(const float2*)&Bs[kk][tx * 2];
            float ar[4] = {a.x, a.y, a.z, a.w};
            #pragma unroll
            for (int i = 0; i < 4; i++) {
                acc[i][0] += ar[i] * bb.x;
                acc[i][1] += ar[i] * bb.y;
            }
        }
        #pragma unroll
        for (int i = 0; i < 4; i++) {
            #pragma unroll
            for (int j = 0; j < 2; j++) {
                float v = acc[i][j] * INV_T;
                if (v > mrun[i]) { srun[i] = srun[i] * __expf(mrun[i] - v) + 1.f; mrun[i] = v; }
                else             { srun[i] += __expf(v - mrun[i]); }
            }
        }
    }
    // reduce across 32 lanes of the warp (each warp = 4 rows)
    #pragma unroll
    for (int i = 0; i < 4; i++) {
        float m = mrun[i], s = srun[i];
        #pragma unroll
        for (int o = 16; o; o >>= 1) {
            float m2 = __shfl_xor_sync(0xffffffffu, m, o);
            float s2 = __shfl_xor_sync(0xffffffffu, s, o);
            float mn = fmaxf(m, m2);
            s = s * __expf(m - mn) + s2 * __expf(m2 - mn);
            m = mn;
        }
        if (tx == 0) {
            int row = m0 + ty * 4 + i;
            float lse = m + logf(s);
            sloss[ty * 4 + i] = lse - g_spcl_diag[b * NSP + row];
        }
    }
    __syncthreads();
    if (tid == 0) {
        float sum = 0.f;
        #pragma unroll
        for (int i = 0; i < 32; i++) sum += sloss[i];
        atomicAdd(out, sum * (1.0f / (NBATCH * NSP)));
    }
}

// ---------------- host launcher -----------------------------------------------
static void* spcl_devptr(const void* sym) {
    void* p = nullptr;
    cudaGetSymbolAddress(&p, sym);
    return p;
}

extern "C" void kernel_launch(void* const* d_in, const int* in_sizes, int n_in,
                              void* d_out, int out_size) {
    const float* features = (const float*)d_in[0];
    const int*   spidx    = (const int*)d_in[1];
    const float* W1  = (const float*)d_in[2];
    const float* b1  = (const float*)d_in[3];
    const float* W2  = (const float*)d_in[4];
    const float* b2  = (const float*)d_in[5];
    const float* Wp1 = (const float*)d_in[6];
    const float* bp1 = (const float*)d_in[7];
    const float* Wp2 = (const float*)d_in[8];
    const float* bp2 = (const float*)d_in[9];
    float* out = (float*)d_out;

    void* p_adj    = spcl_devptr(g_spcl_adj);
    float* p_invdeg = (float*)spcl_devptr(g_spcl_invdeg);
    float* p_spf    = (float*)spcl_devptr(g_spcl_spf);
    float* p_p      = (float*)spcl_devptr(g_spcl_p);
    float* p_h1     = (float*)spcl_devptr(g_spcl_h1);
    float* p_h2     = (float*)spcl_devptr(g_spcl_h2);
    float* p_z1     = (float*)spcl_devptr(g_spcl_z1);
    float* p_z2     = (float*)spcl_devptr(g_spcl_z2);

    // 0) zero adj/cnti/out
    zero_kernel<<<2048, 256>>>(out);
    // 1) counts + rank + binary adjacency (+eye)
    count_adj_kernel<<<dim3(HW / 256, NBATCH), 256>>>(spidx);
    // 2) offsets per batch
    scan_kernel<<<NBATCH, 1024>>>();
    // 3) invdeg
    invdeg_kernel<<<dim3(NSP / 8, NBATCH), 256>>>();
    // 4-5) per batch: transpose into shared fp16 buffer (L2-resident), segment mean
    for (int b = 0; b < NBATCH; b++) {
        transpose_kernel<<<dim3(HW / 64, NC / 64), 256>>>(features, spidx, b);
        segsum_kernel<<<NSP, 128>>>(b);
    }
    // 6) GEMM1: p = spf @ W1^T   (M=NSP, N=HID, K=NC, B T-mode)
    gemm_kernel<<<dim3(HID / TNI, NSP / TMI, NBATCH), 256>>>(
        p_spf, NC, (size_t)NSP * NC, W1, NC, 0, p_p, HID, (size_t)NSP * HID,
        NC, nullptr, nullptr, 2, 1.f);
    // 7) GEMM2: h1 = relu(adj_norm @ p + b1)  (byte-A, sym scale)
    gemm_kernel<<<dim3(HID / TNI, NSP / TMI, NBATCH), 256>>>(
        p_adj, NSP, (size_t)NSP * NSP, p_p, HID, (size_t)NSP * HID, p_h1, HID,
        (size_t)NSP * HID, NSP, b1, p_invdeg, 5, 1.f);
    // 8) GEMM3: h2 = relu(h1 @ W2^T + b2)
    gemm_kernel<<<dim3(HID / TNI, NSP / TMI, NBATCH), 256>>>(
        p_h1, HID, (size_t)NSP * HID, W2, HID, 0, p_h2, HID, (size_t)NSP * HID,
        HID, b2, nullptr, 3, 1.f);
    // 9) GEMM4: z1 = h2 @ Wp1^T + bp1 ; z2 = h2 @ Wp2^T + bp2
    gemm_kernel<<<dim3(ODIM / TNI, NSP / TMI, NBATCH), 256>>>(
        p_h2, HID, (size_t)NSP * HID, Wp1, HID, 0, p_z1, ODIM, (size_t)NSP * ODIM,
        HID, bp1, nullptr, 2, 1.f);
    gemm_kernel<<<dim3(ODIM / TNI, NSP / TMI, NBATCH), 256>>>(
        p_h2, HID, (size_t)NSP * HID, Wp2, HID, 0, p_z2, ODIM, (size_t)NSP * ODIM,
        HID, bp2, nullptr, 2, 1.f);
    // 10) row-normalize + diag
    norm_kernel<<<dim3(NSP / 8, NBATCH), 256>>>();
    // 11) fused sim + logsumexp + loss
    simlse_kernel<<<dim3(NSP / 32, NBATCH), 256>>>(out);
}

// round 7
// speedup vs baseline: 2.5866x; 1.2816x over previous
#include <cuda_runtime.h>
#include <cuda_fp16.h>
#include <math.h>

#define NBATCH 4
#define NC     256
#define HW     65536
#define WIMG   256
#define NSP    1024
#define HID    128
#define ODIM   64
#define INV_T  10.0f

// ---------------- scratch (device globals; no allocation allowed) ----------------
__device__ int    g_cnti[NBATCH * NSP];
__device__ int    g_off[NBATCH * NSP];
__device__ int    g_rank[(size_t)NBATCH * HW];
__device__ unsigned char g_adj[(size_t)NBATCH * NSP * NSP];     // 4 MB
__device__ float  g_invdeg[NBATCH * NSP];
__device__ __half g_adjn[(size_t)NBATCH * NSP * NSP];           // 8 MB normalized adjacency
__device__ __half g_featT16[(size_t)HW * NC];                   // 32 MB, ONE batch at a time
__device__ __half g_spfh[(size_t)NBATCH * NSP * NC];            // [b][s][c] fp16
__device__ __half g_pT[(size_t)NBATCH * HID * NSP];             // [b][j][s] fp16
__device__ __half g_h1[(size_t)NBATCH * NSP * HID];
__device__ __half g_h2[(size_t)NBATCH * NSP * HID];
__device__ __half g_w1h[HID * NC];
__device__ __half g_w2h[HID * HID];
__device__ __half g_wp1h[ODIM * HID];
__device__ __half g_wp2h[ODIM * HID];
__device__ float  g_z1[NBATCH * NSP * ODIM];
__device__ float  g_z2[NBATCH * NSP * ODIM];
__device__ float  g_diag[NBATCH * NSP];

// ---------------- mma helpers ---------------------------------------------------
__device__ __forceinline__ unsigned sptr(const void* p) {
    return (unsigned)__cvta_generic_to_shared(p);
}
__device__ __forceinline__ void ldsm4(unsigned& r0, unsigned& r1, unsigned& r2, unsigned& r3,
                                      unsigned addr) {
    asm volatile("ldmatrix.sync.aligned.m8n8.x4.shared.b16 {%0,%1,%2,%3}, [%4];"
                 : "=r"(r0), "=r"(r1), "=r"(r2), "=r"(r3) : "r"(addr));
}
__device__ __forceinline__ void mma16816(float* d, const unsigned* a, const unsigned* b) {
    asm volatile("mma.sync.aligned.m16n8k16.row.col.f32.f16.f16.f32 "
                 "{%0,%1,%2,%3}, {%4,%5,%6,%7}, {%8,%9}, {%0,%1,%2,%3};"
                 : "+f"(d[0]), "+f"(d[1]), "+f"(d[2]), "+f"(d[3])
                 : "r"(a[0]), "r"(a[1]), "r"(a[2]), "r"(a[3]), "r"(b[0]), "r"(b[1]));
}

// ---------------- zero: adj(bytes) + cnti + out --------------------------------
__global__ __launch_bounds__(256) void zero_kernel(float* d_out) {
    size_t gid = (size_t)blockIdx.x * 256 + threadIdx.x;   // 2048*256, 8B each
    ((uint2*)g_adj)[gid] = make_uint2(0u, 0u);
    if (gid < (NBATCH * NSP) / 4) ((int4*)g_cnti)[gid] = make_int4(0, 0, 0, 0);
    if (gid == 0) d_out[0] = 0.f;
}

// ---------------- counts (+rank) + binary adjacency ----------------------------
__global__ __launch_bounds__(256) void count_adj_kernel(const int* __restrict__ idx) {
    int b = blockIdx.y;
    int p = blockIdx.x * 256 + threadIdx.x;
    const int* ib = idx + (size_t)b * HW;
    int s = ib[p];
    int r = atomicAdd(&g_cnti[b * NSP + s], 1);
    g_rank[(size_t)b * HW + p] = r;
    unsigned char* adjb = g_adj + (size_t)b * NSP * NSP;
    if ((p & (WIMG - 1)) < WIMG - 1) {
        int s2 = ib[p + 1];
        if (s2 != s) { adjb[(size_t)s * NSP + s2] = 1; adjb[(size_t)s2 * NSP + s] = 1; }
    }
    if (p < HW - WIMG) {
        int s2 = ib[p + WIMG];
        if (s2 != s) { adjb[(size_t)s * NSP + s2] = 1; adjb[(size_t)s2 * NSP + s] = 1; }
    }
    if (p < NSP) adjb[(size_t)p * NSP + p] = 1;
}

// ---------------- exclusive scan of counts -> offsets --------------------------
__global__ __launch_bounds__(1024) void scan_kernel() {
    __shared__ int sm[NSP];
    int b = blockIdx.x, t = threadIdx.x;
    int v = g_cnti[b * NSP + t];
    sm[t] = v;
    __syncthreads();
    for (int o = 1; o < NSP; o <<= 1) {
        int x = (t >= o) ? sm[t - o] : 0;
        __syncthreads();
        sm[t] += x;
        __syncthreads();
    }
    g_off[b * NSP + t] = sm[t] - v;
}

// ---------------- invdeg = rsqrt(rowsum(adj)) ----------------------------------
__global__ __launch_bounds__(256) void invdeg_kernel() {
    int b = blockIdx.y;
    int row = blockIdx.x * 8 + (threadIdx.x >> 5);
    int lane = threadIdx.x & 31;
    const uint4* r = (const uint4*)(g_adj + ((size_t)b * NSP + row) * NSP);
    uint4 v1 = r[lane], v2 = r[lane + 32];
    unsigned int s = 0u;
    s = __dp4a(v1.x, 0x01010101u, s); s = __dp4a(v1.y, 0x01010101u, s);
    s = __dp4a(v1.z, 0x01010101u, s); s = __dp4a(v1.w, 0x01010101u, s);
    s = __dp4a(v2.x, 0x01010101u, s); s = __dp4a(v2.y, 0x01010101u, s);
    s = __dp4a(v2.z, 0x01010101u, s); s = __dp4a(v2.w, 0x01010101u, s);
    int si = (int)s;
    #pragma unroll
    for (int o = 16; o; o >>= 1) si += __shfl_xor_sync(0xffffffffu, si, o);
    if (lane == 0) g_invdeg[b * NSP + row] = rsqrtf(fmaxf((float)si, 1.0f));
}

// ---------------- materialize normalized adjacency as fp16 ---------------------
__global__ __launch_bounds__(256) void adjn_kernel() {
    size_t gid = (size_t)blockIdx.x * 256 + threadIdx.x;   // 4096*256 = 1M, 4 elems each
    size_t e = gid * 4;
    int b = (int)(e >> 20);
    int i = (int)((e >> 10) & (NSP - 1));
    int j = (int)(e & (NSP - 1));
    uchar4 a = *(const uchar4*)(g_adj + e);
    float di = g_invdeg[b * NSP + i];
    const float* dj = &g_invdeg[b * NSP + j];
    __half2 h0 = __floats2half2_rn(a.x ? di * dj[0] : 0.f, a.y ? di * dj[1] : 0.f);
    __half2 h1 = __floats2half2_rn(a.z ? di * dj[2] : 0.f, a.w ? di * dj[3] : 0.f);
    uint2 st;
    st.x = *(unsigned*)&h0; st.y = *(unsigned*)&h1;
    ((uint2*)g_adjn)[gid] = st;
}

// ---------------- convert weights to fp16 --------------------------------------
__global__ __launch_bounds__(256) void cvtw_kernel(const float* __restrict__ W1,
                                                   const float* __restrict__ W2,
                                                   const float* __restrict__ Wp1,
                                                   const float* __restrict__ Wp2) {
    int t = blockIdx.x * 256 + threadIdx.x;
    if (t < 32768)      g_w1h[t] = __float2half(W1[t]);
    else if (t < 49152) g_w2h[t - 32768] = __float2half(W2[t - 32768]);
    else if (t < 57344) g_wp1h[t - 49152] = __float2half(Wp1[t - 49152]);
    else                g_wp2h[t - 57344] = __float2half(Wp2[t - 57344]);
}

// ---------------- scatter-transpose: feat [C,HW] -> featT16 [slot][C] ----------
// grid (HW/64, NC/64), 256 threads; one batch per launch  (R4 proven)
__global__ __launch_bounds__(256) void transpose_kernel(const float* __restrict__ feat,
                                                        const int* __restrict__ idx, int b) {
    __shared__ float tile[64][65];
    __shared__ int sl[64];
    int c0 = blockIdx.y * 64, p0 = blockIdx.x * 64;
    int tid = threadIdx.x;
    if (tid < 64) {
        int p = p0 + tid;
        int s = idx[(size_t)b * HW + p];
        sl[tid] = g_off[b * NSP + s] + g_rank[(size_t)b * HW + p];
    }
    int px = tid & 63, cl = tid >> 6;
    const float* f = feat + ((size_t)b * NC + c0) * HW + p0;
    #pragma unroll
    for (int i = 0; i < 16; i++)
        tile[cl + i * 4][px] = f[(size_t)(cl + i * 4) * HW + px];
    __syncthreads();
    int w = tid >> 5, lane = tid & 31;
    __half2* dst = (__half2*)g_featT16;
    #pragma unroll
    for (int i = 0; i < 8; i++) {
        int p = w + i * 8;
        dst[(size_t)sl[p] * (NC / 2) + (c0 >> 1) + lane] =
            __floats2half2_rn(tile[lane * 2][p], tile[lane * 2 + 1][p]);
    }
}

// ---------------- contiguous segment mean -> spfh [b][s][c] fp16 ---------------
__global__ __launch_bounds__(128) void segsum_kernel(int b) {
    int s = blockIdx.x, t = threadIdx.x;
    int start = g_off[b * NSP + s];
    int n = g_cnti[b * NSP + s];
    const __half2* base = (const __half2*)g_featT16 + (size_t)start * (NC / 2) + t;
    float2 a0 = make_float2(0.f, 0.f), a1 = make_float2(0.f, 0.f);
    int r = 0;
    for (; r + 2 <= n; r += 2) {
        float2 x0 = __half22float2(base[(size_t)r * (NC / 2)]);
        float2 x1 = __half22float2(base[(size_t)(r + 1) * (NC / 2)]);
        a0.x += x0.x; a0.y += x0.y; a1.x += x1.x; a1.y += x1.y;
    }
    if (r < n) {
        float2 x0 = __half22float2(base[(size_t)r * (NC / 2)]);
        a0.x += x0.x; a0.y += x0.y;
    }
    float invn = (n > 0) ? 1.f / (float)n : 0.f;
    ((__half2*)g_spfh)[((size_t)b * NSP + s) * (NC / 2) + t] =
        __floats2half2_rn((a0.x + a1.x) * invn, (a0.y + a1.y) * invn);
}

// ---------------- fp16 mma GEMM: C[M,N] = A(row-major [m][k]) @ B([n][k])^T -----
// flags: bit0 relu, bit1 fp16-out, bit2 transposed-out (C[n][m], fp16)
#define GM_BM 64
#define GM_BN 64
#define GM_BK 32
__global__ __launch_bounds__(128) void mma_gemm(
    const __half* __restrict__ A, int lda, size_t sA,
    const __half* __restrict__ B, int ldb, size_t sB,
    void* __restrict__ Cv, int ldc, size_t sC,
    int K, const float* __restrict__ bias, int flags)
{
    __shared__ __half As[GM_BM][GM_BK + 8];
    __shared__ __half Bs[GM_BN][GM_BK + 8];
    int b = blockIdx.z;
    A += (size_t)b * sA;
    B += (size_t)b * sB;
    int m0 = blockIdx.y * GM_BM, n0 = blockIdx.x * GM_BN;
    int tid = threadIdx.x, w = tid >> 5, lane = tid & 31;
    int wm = (w >> 1) * 32, wn = (w & 1) * 32;
    float acc[2][4][4];
    #pragma unroll
    for (int i = 0; i < 2; i++)
        #pragma unroll
        for (int j = 0; j < 4; j++)
            #pragma unroll
            for (int q = 0; q < 4; q++) acc[i][j][q] = 0.f;

    int r8 = lane & 7, grp = lane >> 3;
    for (int k0 = 0; k0 < K; k0 += GM_BK) {
        // Each row has GM_BK=32 halves = 4 uint4; 128 threads cover 64 rows with
        // 2 threads/row, each storing TWO uint4 (16 halves): oo in {0,16}.
        int rr = tid >> 1, oo = (tid & 1) * 16;
        {
            const __half* pa = A + (size_t)(m0 + rr) * lda + k0 + oo;
            *(uint4*)&As[rr][oo]     = *(const uint4*)pa;
            *(uint4*)&As[rr][oo + 8] = *(const uint4*)(pa + 8);
            const __half* pb = B + (size_t)(n0 + rr) * ldb + k0 + oo;
            *(uint4*)&Bs[rr][oo]     = *(const uint4*)pb;
            *(uint4*)&Bs[rr][oo + 8] = *(const uint4*)(pb + 8);
        }
        __syncthreads();
        #pragma unroll
        for (int kk = 0; kk < GM_BK; kk += 16) {
            unsigned af[2][4], bf[4][2];
            #pragma unroll
            for (int i = 0; i < 2; i++) {
                unsigned ad = sptr(&As[wm + i * 16 + r8 + ((grp & 1) << 3)][kk + ((grp & 2) << 2)]);
                ldsm4(af[i][0], af[i][1], af[i][2], af[i][3], ad);
            }
            #pragma unroll
            for (int jp = 0; jp < 2; jp++) {
                unsigned q0, q1, q2, q3;
                unsigned ad = sptr(&Bs[wn + jp * 16 + r8 + ((grp & 2) << 2)][kk + ((grp & 1) << 3)]);
                ldsm4(q0, q1, q2, q3, ad);
                bf[jp * 2][0] = q0;     bf[jp * 2][1] = q1;
                bf[jp * 2 + 1][0] = q2; bf[jp * 2 + 1][1] = q3;
            }
            #pragma unroll
            for (int i = 0; i < 2; i++)
                #pragma unroll
                for (int j = 0; j < 4; j++) mma16816(acc[i][j], af[i], bf[j]);
        }
        __syncthreads();
    }
    int rr = lane >> 2, cg = (lane & 3) * 2;
    #pragma unroll
    for (int i = 0; i < 2; i++) {
        int gm = m0 + wm + i * 16 + rr;
        #pragma unroll
        for (int j = 0; j < 4; j++) {
            int gn = n0 + wn + j * 8 + cg;
            float bx = bias ? bias[gn] : 0.f;
            float by = bias ? bias[gn + 1] : 0.f;
            float v0 = acc[i][j][0] + bx, v1 = acc[i][j][1] + by;
            float v2 = acc[i][j][2] + bx, v3 = acc[i][j][3] + by;
            if (flags & 1) {
                v0 = fmaxf(v0, 0.f); v1 = fmaxf(v1, 0.f);
                v2 = fmaxf(v2, 0.f); v3 = fmaxf(v3, 0.f);
            }
            if (flags & 4) {                       // transposed fp16 out: C[n][m]
                __half* C = (__half*)Cv + (size_t)b * sC;
                C[(size_t)gn * ldc + gm]           = __float2half(v0);
                C[(size_t)(gn + 1) * ldc + gm]     = __float2half(v1);
                C[(size_t)gn * ldc + gm + 8]       = __float2half(v2);
                C[(size_t)(gn + 1) * ldc + gm + 8] = __float2half(v3);
            } else if (flags & 2) {                // fp16 out C[m][n]
                __half* C = (__half*)Cv + (size_t)b * sC;
                *(__half2*)(C + (size_t)gm * ldc + gn) = __floats2half2_rn(v0, v1);
                *(__half2*)(C + (size_t)(gm + 8) * ldc + gn) = __floats2half2_rn(v2, v3);
            } else {                               // fp32 out C[m][n]
                float* C = (float*)Cv + (size_t)b * sC;
                *(float2*)(C + (size_t)gm * ldc + gn) = make_float2(v0, v1);
                *(float2*)(C + (size_t)(gm + 8) * ldc + gn) = make_float2(v2, v3);
            }
        }
    }
}

// ---------------- row-normalize z1, z2 (in place) + diag ------------------------
__global__ __launch_bounds__(256) void norm_kernel() {
    int b = blockIdx.y;
    int row = blockIdx.x * 8 + (threadIdx.x >> 5);
    int lane = threadIdx.x & 31;
    float* z1 = g_z1 + ((size_t)b * NSP + row) * ODIM;
    float* z2 = g_z2 + ((size_t)b * NSP + row) * ODIM;
    float a0 = z1[lane], a1 = z1[lane + 32];
    float ss = a0 * a0 + a1 * a1;
    #pragma unroll
    for (int o = 16; o; o >>= 1) ss += __shfl_xor_sync(0xffffffffu, ss, o);
    float inv = rsqrtf(fmaxf(ss, 1e-30f));
    float a0n = a0 * inv, a1n = a1 * inv;
    z1[lane] = a0n; z1[lane + 32] = a1n;
    float c0 = z2[lane], c1 = z2[lane + 32];
    float ss2 = c0 * c0 + c1 * c1;
    #pragma unroll
    for (int o = 16; o; o >>= 1) ss2 += __shfl_xor_sync(0xffffffffu, ss2, o);
    float inv2 = rsqrtf(fmaxf(ss2, 1e-30f));
    float c0n = c0 * inv2, c1n = c1 * inv2;
    z2[lane] = c0n; z2[lane + 32] = c1n;
    float dd = a0n * c0n + a1n * c1n;
    #pragma unroll
    for (int o = 16; o; o >>= 1) dd += __shfl_xor_sync(0xffffffffu, dd, o);
    if (lane == 0) g_diag[b * NSP + row] = dd * INV_T;
}

// ---------------- fused sim GEMM + online logsumexp + loss ---------------------
__global__ __launch_bounds__(256) void simlse_kernel(float* __restrict__ out) {
    __shared__ float As[ODIM][36];
    __shared__ float Bs[ODIM][66];
    __shared__ float sloss[32];
    int b = blockIdx.y;
    int m0 = blockIdx.x * 32;
    int tid = threadIdx.x;
    int tx = tid & 31, ty = tid >> 5;
    const float* z1 = g_z1 + (size_t)b * NSP * ODIM;
    const float* z2 = g_z2 + (size_t)b * NSP * ODIM;
    {
        int r = tid >> 3, cg = (tid & 7) * 8;
        float4 v1 = *(const float4*)(z1 + (size_t)(m0 + r) * ODIM + cg);
        float4 v2 = *(const float4*)(z1 + (size_t)(m0 + r) * ODIM + cg + 4);
        As[cg + 0][r] = v1.x; As[cg + 1][r] = v1.y; As[cg + 2][r] = v1.z; As[cg + 3][r] = v1.w;
        As[cg + 4][r] = v2.x; As[cg + 5][r] = v2.y; As[cg + 6][r] = v2.z; As[cg + 7][r] = v2.w;
    }
    float mrun[4], srun[4];
    #pragma unroll
    for (int i = 0; i < 4; i++) { mrun[i] = -1e30f; srun[i] = 0.f; }

    for (int n0 = 0; n0 < NSP; n0 += 64) {
        __syncthreads();
        {
            int r = tid >> 2, cg = (tid & 3) * 16;
            #pragma unroll
            for (int q = 0; q < 4; q++) {
                float4 v = *(const float4*)(z2 + (size_t)(n0 + r) * ODIM + cg + q * 4);
                Bs[cg + q * 4 + 0][r] = v.x; Bs[cg + q * 4 + 1][r] = v.y;
                Bs[cg + q * 4 + 2][r] = v.z; Bs[cg + q * 4 + 3][r] = v.w;
            }
        }
        __syncthreads();
        float acc[4][2];
        #pragma unroll
        for (int i = 0; i < 4; i++) { acc[i][0] = 0.f; acc[i][1] = 0.f; }
        #pragma unroll
        for (int kk = 0; kk < ODIM; kk++) {
            float4 a = *(const float4*)&As[kk][ty * 4];
            float2 bb = *(const float2*)&Bs[kk][tx * 2];
            float ar[4] = {a.x, a.y, a.z, a.w};
            #pragma unroll
            for (int i = 0; i < 4; i++) {
                acc[i][0] += ar[i] * bb.x;
                acc[i][1] += ar[i] * bb.y;
            }
        }
        #pragma unroll
        for (int i = 0; i < 4; i++) {
            #pragma unroll
            for (int j = 0; j < 2; j++) {
                float v = acc[i][j] * INV_T;
                if (v > mrun[i]) { srun[i] = srun[i] * __expf(mrun[i] - v) + 1.f; mrun[i] = v; }
                else             { srun[i] += __expf(v - mrun[i]); }
            }
        }
    }
    #pragma unroll
    for (int i = 0; i < 4; i++) {
        float m = mrun[i], s = srun[i];
        #pragma unroll
        for (int o = 16; o; o >>= 1) {
            float m2 = __shfl_xor_sync(0xffffffffu, m, o);
            float s2 = __shfl_xor_sync(0xffffffffu, s, o);
            float mn = fmaxf(m, m2);
            s = s * __expf(m - mn) + s2 * __expf(m2 - mn);
            m = mn;
        }
        if (tx == 0) {
            int row = m0 + ty * 4 + i;
            float lse = m + logf(s);
            sloss[ty * 4 + i] = lse - g_diag[b * NSP + row];
        }
    }
    __syncthreads();
    if (tid == 0) {
        float sum = 0.f;
        #pragma unroll
        for (int i = 0; i < 32; i++) sum += sloss[i];
        atomicAdd(out, sum * (1.0f / (NBATCH * NSP)));
    }
}

// ---------------- host launcher -----------------------------------------------
static void* dvp(const void* sym) {
    void* p = nullptr;
    cudaGetSymbolAddress(&p, sym);
    return p;
}

extern "C" void kernel_launch(void* const* d_in, const int* in_sizes, int n_in,
                              void* d_out, int out_size) {
    const float* features = (const float*)d_in[0];
    const int*   spidx    = (const int*)d_in[1];
    const float* W1  = (const float*)d_in[2];
    const float* b1  = (const float*)d_in[3];
    const float* W2  = (const float*)d_in[4];
    const float* b2  = (const float*)d_in[5];
    const float* Wp1 = (const float*)d_in[6];
    const float* bp1 = (const float*)d_in[7];
    const float* Wp2 = (const float*)d_in[8];
    const float* bp2 = (const float*)d_in[9];
    float* out = (float*)d_out;

    __half* p_adjn = (__half*)dvp(g_adjn);
    __half* p_spfh = (__half*)dvp(g_spfh);
    __half* p_pT   = (__half*)dvp(g_pT);
    __half* p_h1   = (__half*)dvp(g_h1);
    __half* p_h2   = (__half*)dvp(g_h2);
    __half* p_w1h  = (__half*)dvp(g_w1h);
    __half* p_w2h  = (__half*)dvp(g_w2h);
    __half* p_wp1h = (__half*)dvp(g_wp1h);
    __half* p_wp2h = (__half*)dvp(g_wp2h);
    float*  p_z1   = (float*)dvp(g_z1);
    float*  p_z2   = (float*)dvp(g_z2);

    zero_kernel<<<2048, 256>>>(out);
    count_adj_kernel<<<dim3(HW / 256, NBATCH), 256>>>(spidx);
    scan_kernel<<<NBATCH, 1024>>>();
    invdeg_kernel<<<dim3(NSP / 8, NBATCH), 256>>>();
    adjn_kernel<<<4096, 256>>>();
    cvtw_kernel<<<256, 256>>>(W1, W2, Wp1, Wp2);
    for (int b = 0; b < NBATCH; b++) {
        transpose_kernel<<<dim3(HW / 64, NC / 64), 256>>>(features, spidx, b);
        segsum_kernel<<<NSP, 128>>>(b);
    }
    // gemm1: pT[j][s] = (spfh @ W1^T)^T   M=1024(s) N=128(j) K=256, transposed fp16 out
    mma_gemm<<<dim3(HID / GM_BN, NSP / GM_BM, NBATCH), 128>>>(
        p_spfh, NC, (size_t)NSP * NC,
        p_w1h, NC, 0,
        p_pT, NSP, (size_t)HID * NSP,
        NC, nullptr, 4);
    // gemm2: h1 = relu(adjn @ pT^T + b1)   M=1024 N=128 K=1024, fp16 out
    mma_gemm<<<dim3(HID / GM_BN, NSP / GM_BM, NBATCH), 128>>>(
        p_adjn, NSP, (size_t)NSP * NSP,
        p_pT, NSP, (size_t)HID * NSP,
        p_h1, HID, (size_t)NSP * HID,
        NSP, b1, 3);
    // gemm3: h2 = relu(h1 @ W2^T + b2)     M=1024 N=128 K=128
    mma_gemm<<<dim3(HID / GM_BN, NSP / GM_BM, NBATCH), 128>>>(
        p_h1, HID, (size_t)NSP * HID,
        p_w2h, HID, 0,
        p_h2, HID, (size_t)NSP * HID,
        HID, b2, 3);
    // gemm4: z = h2 @ Wp^T + bp (fp32 out)
    mma_gemm<<<dim3(ODIM / GM_BN, NSP / GM_BM, NBATCH), 128>>>(
        p_h2, HID, (size_t)NSP * HID,
        p_wp1h, HID, 0,
        p_z1, ODIM, (size_t)NSP * ODIM,
        HID, bp1, 0);
    mma_gemm<<<dim3(ODIM / GM_BN, NSP / GM_BM, NBATCH), 128>>>(
        p_h2, HID, (size_t)NSP * HID,
        p_wp2h, HID, 0,
        p_z2, ODIM, (size_t)NSP * ODIM,
        HID, bp2, 0);
    norm_kernel<<<dim3(NSP / 8, NBATCH), 256>>>();
    simlse_kernel<<<dim3(NSP / 32, NBATCH), 256>>>(out);
}